// round 1
// baseline (speedup 1.0000x reference)
#include <cuda_runtime.h>
#include <math.h>

#define Bb   2
#define Ss   2048
#define Dd   2048
#define Hh   16
#define Dhh  128
#define Mrows (Bb * Ss)   // 4096
#define KPAD 68

__device__ float g_Q[(size_t)Mrows * Dd];
__device__ float g_K[(size_t)Mrows * Dd];
__device__ float g_V[(size_t)Mrows * Dd];

// ---------------------------------------------------------------------------
// C = A @ W^T  (A: [4096,2048], W: [2048,2048], both row-major, K contiguous)
// 128x128 block tile, BK=8, 256 threads, 8x8 microtile.
// ---------------------------------------------------------------------------
__global__ void __launch_bounds__(256) sgemm_nt(const float* __restrict__ A,
                                                const float* __restrict__ W,
                                                float* __restrict__ C) {
    __shared__ float As[8][128];
    __shared__ float Bs[8][128];
    const int tid = threadIdx.x;
    const int m0 = blockIdx.y * 128, n0 = blockIdx.x * 128;
    const int lr = tid >> 1;          // 0..127
    const int lc = (tid & 1) * 4;     // 0 or 4
    const float* Ap = A + (size_t)(m0 + lr) * Dd + lc;
    const float* Wp = W + (size_t)(n0 + lr) * Dd + lc;
    const int ty = tid >> 4, tx = tid & 15;

    float acc[8][8];
#pragma unroll
    for (int i = 0; i < 8; i++)
#pragma unroll
        for (int j = 0; j < 8; j++) acc[i][j] = 0.f;

    for (int k0 = 0; k0 < Dd; k0 += 8) {
        float4 av = *(const float4*)(Ap + k0);
        float4 wv = *(const float4*)(Wp + k0);
        __syncthreads();
        As[lc + 0][lr] = av.x; As[lc + 1][lr] = av.y;
        As[lc + 2][lr] = av.z; As[lc + 3][lr] = av.w;
        Bs[lc + 0][lr] = wv.x; Bs[lc + 1][lr] = wv.y;
        Bs[lc + 2][lr] = wv.z; Bs[lc + 3][lr] = wv.w;
        __syncthreads();
#pragma unroll
        for (int kk = 0; kk < 8; ++kk) {
            float a[8], b[8];
            *(float4*)(a)     = *(const float4*)&As[kk][ty * 8];
            *(float4*)(a + 4) = *(const float4*)&As[kk][ty * 8 + 4];
            *(float4*)(b)     = *(const float4*)&Bs[kk][tx * 8];
            *(float4*)(b + 4) = *(const float4*)&Bs[kk][tx * 8 + 4];
#pragma unroll
            for (int i = 0; i < 8; i++)
#pragma unroll
                for (int j = 0; j < 8; j++)
                    acc[i][j] = fmaf(a[i], b[j], acc[i][j]);
        }
    }
#pragma unroll
    for (int i = 0; i < 8; i++) {
        float* cp = C + (size_t)(m0 + ty * 8 + i) * Dd + n0 + tx * 8;
        *(float4*)cp       = make_float4(acc[i][0], acc[i][1], acc[i][2], acc[i][3]);
        *(float4*)(cp + 4) = make_float4(acc[i][4], acc[i][5], acc[i][6], acc[i][7]);
    }
}

// ---------------------------------------------------------------------------
// Interleaved RoPE on Q and K in place.
// ---------------------------------------------------------------------------
__global__ void rope_kernel(const float* __restrict__ cosT,
                            const float* __restrict__ sinT) {
    size_t i = (size_t)blockIdx.x * blockDim.x + threadIdx.x; // pair index
    int colp = (int)(i & (Dd / 2 - 1));      // 0..1023
    size_t row = i >> 10;                    // b*S + s
    int s = (int)(row & (Ss - 1));
    int h = colp >> 6, p = colp & 63;
    float c  = cosT[s * Dhh + 2 * p];
    float sn = sinT[s * Dhh + 2 * p];
    size_t base = row * Dd + h * Dhh + 2 * p;
    float2 q = *(float2*)&g_Q[base];
    float2 k = *(float2*)&g_K[base];
    float2 qo, ko;
    qo.x = q.x * c - q.y * sn;  qo.y = q.y * c + q.x * sn;
    ko.x = k.x * c - k.y * sn;  ko.y = k.y * c + k.x * sn;
    *(float2*)&g_Q[base] = qo;
    *(float2*)&g_K[base] = ko;
}

// ---------------------------------------------------------------------------
// Causal flash attention + final softmax over Dh.
// Grid: (S/64, B*H). Block: 256 threads (ty=tid/16, tx=tid%16).
// Thread owns score rows ty*4..+3 (4x4 score microtile, 4x8 O microtile).
// ---------------------------------------------------------------------------
__global__ void __launch_bounds__(256) attn_kernel(float* __restrict__ out) {
    extern __shared__ float sm[];
    float* Qs  = sm;                     // 64 x 128
    float* KsT = Qs + 64 * 128;          // 128 x KPAD (transposed K tile)
    float* Vs  = KsT + 128 * KPAD;       // 64 x 128
    float* Ps  = Vs + 64 * 128;          // 64 x 64

    const int qt = blockIdx.x, bh = blockIdx.y;
    const int b = bh >> 4, h = bh & 15;
    const int tid = threadIdx.x, ty = tid >> 4, tx = tid & 15;
    const size_t base = ((size_t)b * Ss) * Dd + h * Dhh;
    const float scale = 0.08838834764831845f; // 1/sqrt(128)

    // Load Q tile (pre-scaled)
    for (int e = tid * 4; e < 64 * 128; e += 1024) {
        int r = e >> 7, c = e & 127;
        float4 v = *(const float4*)&g_Q[base + (size_t)(qt * 64 + r) * Dd + c];
        v.x *= scale; v.y *= scale; v.z *= scale; v.w *= scale;
        *(float4*)&Qs[r * 128 + c] = v;
    }

    float acc[4][8];
#pragma unroll
    for (int i = 0; i < 4; i++)
#pragma unroll
        for (int c = 0; c < 8; c++) acc[i][c] = 0.f;
    float mrow[4], lrow[4];
#pragma unroll
    for (int i = 0; i < 4; i++) { mrow[i] = -1e30f; lrow[i] = 0.f; }

    for (int j = 0; j <= qt; ++j) {
        __syncthreads();  // prev PV done before overwriting tiles
        // Load K tile transposed (coalesced gmem scalar reads)
        for (int e = tid; e < 64 * 128; e += 256) {
            int n = e >> 7, d = e & 127;
            KsT[d * KPAD + n] = g_K[base + (size_t)(j * 64 + n) * Dd + d];
        }
        // Load V tile row-major
        for (int e = tid * 4; e < 64 * 128; e += 1024) {
            int n = e >> 7, d = e & 127;
            *(float4*)&Vs[n * 128 + d] =
                *(const float4*)&g_V[base + (size_t)(j * 64 + n) * Dd + d];
        }
        __syncthreads();

        // Scores: 4x4 microtile
        float s4[4][4];
#pragma unroll
        for (int i = 0; i < 4; i++)
#pragma unroll
            for (int jj = 0; jj < 4; jj++) s4[i][jj] = 0.f;

#pragma unroll 4
        for (int kk = 0; kk < 128; ++kk) {
            float4 bv = *(const float4*)&KsT[kk * KPAD + tx * 4];
            float bb[4] = {bv.x, bv.y, bv.z, bv.w};
            float a[4];
#pragma unroll
            for (int i = 0; i < 4; i++) a[i] = Qs[(ty * 4 + i) * 128 + kk];
#pragma unroll
            for (int i = 0; i < 4; i++)
#pragma unroll
                for (int jj = 0; jj < 4; jj++)
                    s4[i][jj] = fmaf(a[i], bb[jj], s4[i][jj]);
        }

        if (j == qt) {
#pragma unroll
            for (int i = 0; i < 4; i++)
#pragma unroll
                for (int jj = 0; jj < 4; jj++)
                    if (tx * 4 + jj > ty * 4 + i) s4[i][jj] = -1e30f;
        }

        // Online softmax update (row stats replicated across the 16-lane group)
#pragma unroll
        for (int i = 0; i < 4; i++) {
            float mx = fmaxf(fmaxf(s4[i][0], s4[i][1]), fmaxf(s4[i][2], s4[i][3]));
            mx = fmaxf(mx, __shfl_xor_sync(0xffffffffu, mx, 1, 16));
            mx = fmaxf(mx, __shfl_xor_sync(0xffffffffu, mx, 2, 16));
            mx = fmaxf(mx, __shfl_xor_sync(0xffffffffu, mx, 4, 16));
            mx = fmaxf(mx, __shfl_xor_sync(0xffffffffu, mx, 8, 16));
            float mnew = fmaxf(mrow[i], mx);
            float f = __expf(mrow[i] - mnew);
            mrow[i] = mnew;
            float ps = 0.f;
#pragma unroll
            for (int jj = 0; jj < 4; jj++) {
                s4[i][jj] = __expf(s4[i][jj] - mnew);
                ps += s4[i][jj];
            }
            ps += __shfl_xor_sync(0xffffffffu, ps, 1, 16);
            ps += __shfl_xor_sync(0xffffffffu, ps, 2, 16);
            ps += __shfl_xor_sync(0xffffffffu, ps, 4, 16);
            ps += __shfl_xor_sync(0xffffffffu, ps, 8, 16);
            lrow[i] = lrow[i] * f + ps;
#pragma unroll
            for (int c = 0; c < 8; c++) acc[i][c] *= f;
            *(float4*)&Ps[(ty * 4 + i) * 64 + tx * 4] =
                make_float4(s4[i][0], s4[i][1], s4[i][2], s4[i][3]);
        }
        __syncthreads();

        // O += P @ V  (4x8 microtile)
#pragma unroll 2
        for (int kk = 0; kk < 64; ++kk) {
            float4 v0 = *(const float4*)&Vs[kk * 128 + tx * 8];
            float4 v1 = *(const float4*)&Vs[kk * 128 + tx * 8 + 4];
            float vv[8] = {v0.x, v0.y, v0.z, v0.w, v1.x, v1.y, v1.z, v1.w};
            float a[4];
#pragma unroll
            for (int i = 0; i < 4; i++) a[i] = Ps[(ty * 4 + i) * 64 + kk];
#pragma unroll
            for (int i = 0; i < 4; i++)
#pragma unroll
                for (int c = 0; c < 8; c++)
                    acc[i][c] = fmaf(a[i], vv[c], acc[i][c]);
        }
    }

    // Finalize: divide by l, then softmax over the 128 head dims, write out.
    const int qrow = qt * 64 + ty * 4;
#pragma unroll
    for (int i = 0; i < 4; i++) {
        float inv = 1.f / lrow[i];
#pragma unroll
        for (int c = 0; c < 8; c++) acc[i][c] *= inv;
        float mx = acc[i][0];
#pragma unroll
        for (int c = 1; c < 8; c++) mx = fmaxf(mx, acc[i][c]);
        mx = fmaxf(mx, __shfl_xor_sync(0xffffffffu, mx, 1, 16));
        mx = fmaxf(mx, __shfl_xor_sync(0xffffffffu, mx, 2, 16));
        mx = fmaxf(mx, __shfl_xor_sync(0xffffffffu, mx, 4, 16));
        mx = fmaxf(mx, __shfl_xor_sync(0xffffffffu, mx, 8, 16));
        float sum = 0.f;
#pragma unroll
        for (int c = 0; c < 8; c++) {
            acc[i][c] = __expf(acc[i][c] - mx);
            sum += acc[i][c];
        }
        sum += __shfl_xor_sync(0xffffffffu, sum, 1, 16);
        sum += __shfl_xor_sync(0xffffffffu, sum, 2, 16);
        sum += __shfl_xor_sync(0xffffffffu, sum, 4, 16);
        sum += __shfl_xor_sync(0xffffffffu, sum, 8, 16);
        float r = 1.f / sum;
        float* op = out + base + (size_t)(qrow + i) * Dd + tx * 8;
        *(float4*)op       = make_float4(acc[i][0] * r, acc[i][1] * r,
                                         acc[i][2] * r, acc[i][3] * r);
        *(float4*)(op + 4) = make_float4(acc[i][4] * r, acc[i][5] * r,
                                         acc[i][6] * r, acc[i][7] * r);
    }
}

static const size_t ATTN_SMEM = (64 * 128 + 128 * KPAD + 64 * 128 + 64 * 64) * sizeof(float);

extern "C" void kernel_launch(void* const* d_in, const int* in_sizes, int n_in,
                              void* d_out, int out_size) {
    const float* x  = (const float*)d_in[0];
    const float* wq = (const float*)d_in[1];
    const float* wk = (const float*)d_in[2];
    const float* wv = (const float*)d_in[3];
    const float* rc = (const float*)d_in[4];
    const float* rs = (const float*)d_in[5];
    float* out = (float*)d_out;

    float *Qp, *Kp, *Vp;
    cudaGetSymbolAddress((void**)&Qp, g_Q);
    cudaGetSymbolAddress((void**)&Kp, g_K);
    cudaGetSymbolAddress((void**)&Vp, g_V);

    cudaFuncSetAttribute(attn_kernel, cudaFuncAttributeMaxDynamicSharedMemorySize,
                         (int)ATTN_SMEM);

    dim3 gg(Dd / 128, Mrows / 128);      // (16, 32)
    sgemm_nt<<<gg, 256>>>(x, wq, Qp);
    sgemm_nt<<<gg, 256>>>(x, wk, Kp);
    sgemm_nt<<<gg, 256>>>(x, wv, Vp);

    rope_kernel<<<(Mrows * (Dd / 2)) / 256, 256>>>(rc, rs);

    attn_kernel<<<dim3(Ss / 64, Bb * Hh), 256, ATTN_SMEM>>>(out);
}

// round 2
// speedup vs baseline: 1.8398x; 1.8398x over previous
#include <cuda_runtime.h>
#include <math.h>
#include <stdint.h>

#define Bb   2
#define Ss   2048
#define Dd   2048
#define Hh   16
#define Dhh  128
#define Mrows (Bb * Ss)   // 4096
#define KPAD 68

__device__ float g_Q[(size_t)Mrows * Dd];
__device__ float g_K[(size_t)Mrows * Dd];
__device__ float g_V[(size_t)Mrows * Dd];

__device__ __forceinline__ uint32_t f2tf32(float x) {
    uint32_t u;
    asm("cvt.rna.tf32.f32 %0, %1;" : "=r"(u) : "f"(x));
    return u;
}

// ---------------------------------------------------------------------------
// C = A @ W^T via tf32 mma.sync.m16n8k8.
// A: [4096,2048], W: [2048,2048], both row-major (K contiguous).
// Block tile 128x128, BK=32, 256 threads = 8 warps (2x4), warp tile 64x32.
// Smem rows padded to 36 floats: fragment-load bank = (4m+k)%32 is bijective
// over the 32 lanes (m: 8 consecutive, k: 4 consecutive) -> conflict-free,
// and float4 global-staging stores stay 16B-aligned.
// ---------------------------------------------------------------------------
__global__ void __launch_bounds__(256) tgemm_nt(const float* __restrict__ A,
                                                const float* __restrict__ W,
                                                float* __restrict__ C) {
    __shared__ uint32_t As[128][36];
    __shared__ uint32_t Bs[128][36];
    const int tid = threadIdx.x;
    const int m0 = blockIdx.y * 128, n0 = blockIdx.x * 128;
    const int wid = tid >> 5, lane = tid & 31;
    const int wm = (wid >> 2) * 64;     // 0 or 64
    const int wn = (wid & 3) * 32;      // 0,32,64,96
    const int g = lane >> 2, tg = lane & 3;
    const int lr = tid >> 3;            // 0..31
    const int lc = (tid & 7) * 4;       // 0,4,...,28

    const float* Ap = A + (size_t)m0 * Dd;
    const float* Wp = W + (size_t)n0 * Dd;

    float acc[4][4][4];
#pragma unroll
    for (int i = 0; i < 4; i++)
#pragma unroll
        for (int j = 0; j < 4; j++)
#pragma unroll
            for (int r = 0; r < 4; r++) acc[i][j][r] = 0.f;

    float4 ra[4], rb[4];
#pragma unroll
    for (int i = 0; i < 4; i++) {
        ra[i] = *(const float4*)(Ap + (size_t)(lr + 32 * i) * Dd + lc);
        rb[i] = *(const float4*)(Wp + (size_t)(lr + 32 * i) * Dd + lc);
    }

    for (int k0 = 0; k0 < Dd; k0 += 32) {
        __syncthreads();
#pragma unroll
        for (int i = 0; i < 4; i++) {
            uint32_t* ap = &As[lr + 32 * i][lc];
            ap[0] = f2tf32(ra[i].x); ap[1] = f2tf32(ra[i].y);
            ap[2] = f2tf32(ra[i].z); ap[3] = f2tf32(ra[i].w);
            uint32_t* bp = &Bs[lr + 32 * i][lc];
            bp[0] = f2tf32(rb[i].x); bp[1] = f2tf32(rb[i].y);
            bp[2] = f2tf32(rb[i].z); bp[3] = f2tf32(rb[i].w);
        }
        __syncthreads();

        if (k0 + 32 < Dd) {  // prefetch next tiles into registers
#pragma unroll
            for (int i = 0; i < 4; i++) {
                ra[i] = *(const float4*)(Ap + (size_t)(lr + 32 * i) * Dd + k0 + 32 + lc);
                rb[i] = *(const float4*)(Wp + (size_t)(lr + 32 * i) * Dd + k0 + 32 + lc);
            }
        }

#pragma unroll
        for (int ks = 0; ks < 4; ++ks) {
            const int kb = ks * 8;
            uint32_t af[4][4], bf[4][2];
#pragma unroll
            for (int mi = 0; mi < 4; mi++) {
                const int row = wm + mi * 16;
                af[mi][0] = As[row + g][kb + tg];
                af[mi][1] = As[row + g + 8][kb + tg];
                af[mi][2] = As[row + g][kb + tg + 4];
                af[mi][3] = As[row + g + 8][kb + tg + 4];
            }
#pragma unroll
            for (int ni = 0; ni < 4; ni++) {
                const int col = wn + ni * 8;
                bf[ni][0] = Bs[col + g][kb + tg];
                bf[ni][1] = Bs[col + g][kb + tg + 4];
            }
#pragma unroll
            for (int mi = 0; mi < 4; mi++)
#pragma unroll
                for (int ni = 0; ni < 4; ni++) {
                    asm volatile(
                        "mma.sync.aligned.m16n8k8.row.col.f32.tf32.tf32.f32 "
                        "{%0,%1,%2,%3}, {%4,%5,%6,%7}, {%8,%9}, {%0,%1,%2,%3};"
                        : "+f"(acc[mi][ni][0]), "+f"(acc[mi][ni][1]),
                          "+f"(acc[mi][ni][2]), "+f"(acc[mi][ni][3])
                        : "r"(af[mi][0]), "r"(af[mi][1]), "r"(af[mi][2]), "r"(af[mi][3]),
                          "r"(bf[ni][0]), "r"(bf[ni][1]));
                }
        }
    }

#pragma unroll
    for (int mi = 0; mi < 4; mi++)
#pragma unroll
        for (int ni = 0; ni < 4; ni++) {
            const int r0 = m0 + wm + mi * 16 + g;
            const int cc = n0 + wn + ni * 8 + 2 * tg;
            *(float2*)&C[(size_t)r0 * Dd + cc] =
                make_float2(acc[mi][ni][0], acc[mi][ni][1]);
            *(float2*)&C[(size_t)(r0 + 8) * Dd + cc] =
                make_float2(acc[mi][ni][2], acc[mi][ni][3]);
        }
}

// ---------------------------------------------------------------------------
// Interleaved RoPE on Q and K in place.
// ---------------------------------------------------------------------------
__global__ void rope_kernel(const float* __restrict__ cosT,
                            const float* __restrict__ sinT) {
    size_t i = (size_t)blockIdx.x * blockDim.x + threadIdx.x; // pair index
    int colp = (int)(i & (Dd / 2 - 1));      // 0..1023
    size_t row = i >> 10;                    // b*S + s
    int s = (int)(row & (Ss - 1));
    int h = colp >> 6, p = colp & 63;
    float c  = cosT[s * Dhh + 2 * p];
    float sn = sinT[s * Dhh + 2 * p];
    size_t base = row * Dd + h * Dhh + 2 * p;
    float2 q = *(float2*)&g_Q[base];
    float2 k = *(float2*)&g_K[base];
    float2 qo, ko;
    qo.x = q.x * c - q.y * sn;  qo.y = q.y * c + q.x * sn;
    ko.x = k.x * c - k.y * sn;  ko.y = k.y * c + k.x * sn;
    *(float2*)&g_Q[base] = qo;
    *(float2*)&g_K[base] = ko;
}

// ---------------------------------------------------------------------------
// Causal flash attention + final softmax over Dh (f32, unchanged from R0).
// Grid: (S/64, B*H). Block: 256 threads (ty=tid/16, tx=tid%16).
// ---------------------------------------------------------------------------
__global__ void __launch_bounds__(256) attn_kernel(float* __restrict__ out) {
    extern __shared__ float sm[];
    float* Qs  = sm;                     // 64 x 128
    float* KsT = Qs + 64 * 128;          // 128 x KPAD (transposed K tile)
    float* Vs  = KsT + 128 * KPAD;       // 64 x 128
    float* Ps  = Vs + 64 * 128;          // 64 x 64

    const int qt = blockIdx.x, bh = blockIdx.y;
    const int b = bh >> 4, h = bh & 15;
    const int tid = threadIdx.x, ty = tid >> 4, tx = tid & 15;
    const size_t base = ((size_t)b * Ss) * Dd + h * Dhh;
    const float scale = 0.08838834764831845f; // 1/sqrt(128)

    for (int e = tid * 4; e < 64 * 128; e += 1024) {
        int r = e >> 7, c = e & 127;
        float4 v = *(const float4*)&g_Q[base + (size_t)(qt * 64 + r) * Dd + c];
        v.x *= scale; v.y *= scale; v.z *= scale; v.w *= scale;
        *(float4*)&Qs[r * 128 + c] = v;
    }

    float acc[4][8];
#pragma unroll
    for (int i = 0; i < 4; i++)
#pragma unroll
        for (int c = 0; c < 8; c++) acc[i][c] = 0.f;
    float mrow[4], lrow[4];
#pragma unroll
    for (int i = 0; i < 4; i++) { mrow[i] = -1e30f; lrow[i] = 0.f; }

    for (int j = 0; j <= qt; ++j) {
        __syncthreads();
        for (int e = tid; e < 64 * 128; e += 256) {
            int n = e >> 7, d = e & 127;
            KsT[d * KPAD + n] = g_K[base + (size_t)(j * 64 + n) * Dd + d];
        }
        for (int e = tid * 4; e < 64 * 128; e += 1024) {
            int n = e >> 7, d = e & 127;
            *(float4*)&Vs[n * 128 + d] =
                *(const float4*)&g_V[base + (size_t)(j * 64 + n) * Dd + d];
        }
        __syncthreads();

        float s4[4][4];
#pragma unroll
        for (int i = 0; i < 4; i++)
#pragma unroll
            for (int jj = 0; jj < 4; jj++) s4[i][jj] = 0.f;

#pragma unroll 4
        for (int kk = 0; kk < 128; ++kk) {
            float4 bv = *(const float4*)&KsT[kk * KPAD + tx * 4];
            float bb[4] = {bv.x, bv.y, bv.z, bv.w};
            float a[4];
#pragma unroll
            for (int i = 0; i < 4; i++) a[i] = Qs[(ty * 4 + i) * 128 + kk];
#pragma unroll
            for (int i = 0; i < 4; i++)
#pragma unroll
                for (int jj = 0; jj < 4; jj++)
                    s4[i][jj] = fmaf(a[i], bb[jj], s4[i][jj]);
        }

        if (j == qt) {
#pragma unroll
            for (int i = 0; i < 4; i++)
#pragma unroll
                for (int jj = 0; jj < 4; jj++)
                    if (tx * 4 + jj > ty * 4 + i) s4[i][jj] = -1e30f;
        }

#pragma unroll
        for (int i = 0; i < 4; i++) {
            float mx = fmaxf(fmaxf(s4[i][0], s4[i][1]), fmaxf(s4[i][2], s4[i][3]));
            mx = fmaxf(mx, __shfl_xor_sync(0xffffffffu, mx, 1, 16));
            mx = fmaxf(mx, __shfl_xor_sync(0xffffffffu, mx, 2, 16));
            mx = fmaxf(mx, __shfl_xor_sync(0xffffffffu, mx, 4, 16));
            mx = fmaxf(mx, __shfl_xor_sync(0xffffffffu, mx, 8, 16));
            float mnew = fmaxf(mrow[i], mx);
            float f = __expf(mrow[i] - mnew);
            mrow[i] = mnew;
            float ps = 0.f;
#pragma unroll
            for (int jj = 0; jj < 4; jj++) {
                s4[i][jj] = __expf(s4[i][jj] - mnew);
                ps += s4[i][jj];
            }
            ps += __shfl_xor_sync(0xffffffffu, ps, 1, 16);
            ps += __shfl_xor_sync(0xffffffffu, ps, 2, 16);
            ps += __shfl_xor_sync(0xffffffffu, ps, 4, 16);
            ps += __shfl_xor_sync(0xffffffffu, ps, 8, 16);
            lrow[i] = lrow[i] * f + ps;
#pragma unroll
            for (int c = 0; c < 8; c++) acc[i][c] *= f;
            *(float4*)&Ps[(ty * 4 + i) * 64 + tx * 4] =
                make_float4(s4[i][0], s4[i][1], s4[i][2], s4[i][3]);
        }
        __syncthreads();

#pragma unroll 2
        for (int kk = 0; kk < 64; ++kk) {
            float4 v0 = *(const float4*)&Vs[kk * 128 + tx * 8];
            float4 v1 = *(const float4*)&Vs[kk * 128 + tx * 8 + 4];
            float vv[8] = {v0.x, v0.y, v0.z, v0.w, v1.x, v1.y, v1.z, v1.w};
            float a[4];
#pragma unroll
            for (int i = 0; i < 4; i++) a[i] = Ps[(ty * 4 + i) * 64 + kk];
#pragma unroll
            for (int i = 0; i < 4; i++)
#pragma unroll
                for (int c = 0; c < 8; c++)
                    acc[i][c] = fmaf(a[i], vv[c], acc[i][c]);
        }
    }

    const int qrow = qt * 64 + ty * 4;
#pragma unroll
    for (int i = 0; i < 4; i++) {
        float inv = 1.f / lrow[i];
#pragma unroll
        for (int c = 0; c < 8; c++) acc[i][c] *= inv;
        float mx = acc[i][0];
#pragma unroll
        for (int c = 1; c < 8; c++) mx = fmaxf(mx, acc[i][c]);
        mx = fmaxf(mx, __shfl_xor_sync(0xffffffffu, mx, 1, 16));
        mx = fmaxf(mx, __shfl_xor_sync(0xffffffffu, mx, 2, 16));
        mx = fmaxf(mx, __shfl_xor_sync(0xffffffffu, mx, 4, 16));
        mx = fmaxf(mx, __shfl_xor_sync(0xffffffffu, mx, 8, 16));
        float sum = 0.f;
#pragma unroll
        for (int c = 0; c < 8; c++) {
            acc[i][c] = __expf(acc[i][c] - mx);
            sum += acc[i][c];
        }
        sum += __shfl_xor_sync(0xffffffffu, sum, 1, 16);
        sum += __shfl_xor_sync(0xffffffffu, sum, 2, 16);
        sum += __shfl_xor_sync(0xffffffffu, sum, 4, 16);
        sum += __shfl_xor_sync(0xffffffffu, sum, 8, 16);
        float r = 1.f / sum;
        float* op = out + base + (size_t)(qrow + i) * Dd + tx * 8;
        *(float4*)op       = make_float4(acc[i][0] * r, acc[i][1] * r,
                                         acc[i][2] * r, acc[i][3] * r);
        *(float4*)(op + 4) = make_float4(acc[i][4] * r, acc[i][5] * r,
                                         acc[i][6] * r, acc[i][7] * r);
    }
}

static const size_t ATTN_SMEM = (64 * 128 + 128 * KPAD + 64 * 128 + 64 * 64) * sizeof(float);

extern "C" void kernel_launch(void* const* d_in, const int* in_sizes, int n_in,
                              void* d_out, int out_size) {
    const float* x  = (const float*)d_in[0];
    const float* wq = (const float*)d_in[1];
    const float* wk = (const float*)d_in[2];
    const float* wv = (const float*)d_in[3];
    const float* rc = (const float*)d_in[4];
    const float* rs = (const float*)d_in[5];
    float* out = (float*)d_out;

    float *Qp, *Kp, *Vp;
    cudaGetSymbolAddress((void**)&Qp, g_Q);
    cudaGetSymbolAddress((void**)&Kp, g_K);
    cudaGetSymbolAddress((void**)&Vp, g_V);

    cudaFuncSetAttribute(attn_kernel, cudaFuncAttributeMaxDynamicSharedMemorySize,
                         (int)ATTN_SMEM);

    dim3 gg(Dd / 128, Mrows / 128);      // (16, 32)
    tgemm_nt<<<gg, 256>>>(x, wq, Qp);
    tgemm_nt<<<gg, 256>>>(x, wk, Kp);
    tgemm_nt<<<gg, 256>>>(x, wv, Vp);

    rope_kernel<<<(Mrows * (Dd / 2)) / 256, 256>>>(rc, rs);

    attn_kernel<<<dim3(Ss / 64, Bb * Hh), 256, ATTN_SMEM>>>(out);
}

// round 3
// speedup vs baseline: 3.7942x; 2.0622x over previous
#include <cuda_runtime.h>
#include <math.h>
#include <stdint.h>

#define Bb   2
#define Ss   2048
#define Dd   2048
#define Hh   16
#define Dhh  128
#define Mrows (Bb * Ss)   // 4096

__device__ float g_Q[(size_t)Mrows * Dd];
__device__ float g_K[(size_t)Mrows * Dd];
__device__ float g_V[(size_t)Mrows * Dd];

__device__ __forceinline__ uint32_t f2tf32(float x) {
    uint32_t u;
    asm("cvt.rna.tf32.f32 %0, %1;" : "=r"(u) : "f"(x));
    return u;
}
__device__ __forceinline__ float ex2(float x) {
    float y;
    asm("ex2.approx.ftz.f32 %0, %1;" : "=f"(y) : "f"(x));
    return y;
}
__device__ __forceinline__ uint32_t smem_u32(const void* p) {
    uint32_t a;
    asm("{ .reg .u64 t; cvta.to.shared.u64 t, %1; cvt.u32.u64 %0, t; }"
        : "=r"(a) : "l"(p));
    return a;
}
__device__ __forceinline__ void cpa16(uint32_t dst, const void* src) {
    asm volatile("cp.async.cg.shared.global [%0], [%1], 16;" :: "r"(dst), "l"(src));
}
__device__ __forceinline__ void mma8(float* c, uint32_t a0, uint32_t a1,
                                     uint32_t a2, uint32_t a3,
                                     uint32_t b0, uint32_t b1) {
    asm volatile(
        "mma.sync.aligned.m16n8k8.row.col.f32.tf32.tf32.f32 "
        "{%0,%1,%2,%3}, {%4,%5,%6,%7}, {%8,%9}, {%0,%1,%2,%3};"
        : "+f"(c[0]), "+f"(c[1]), "+f"(c[2]), "+f"(c[3])
        : "r"(a0), "r"(a1), "r"(a2), "r"(a3), "r"(b0), "r"(b1));
}

// ---------------------------------------------------------------------------
// C = A @ W^T via tf32 mma (unchanged from R1).
// ---------------------------------------------------------------------------
__global__ void __launch_bounds__(256) tgemm_nt(const float* __restrict__ A,
                                                const float* __restrict__ W,
                                                float* __restrict__ C) {
    __shared__ uint32_t As[128][36];
    __shared__ uint32_t Bs[128][36];
    const int tid = threadIdx.x;
    const int m0 = blockIdx.y * 128, n0 = blockIdx.x * 128;
    const int wid = tid >> 5, lane = tid & 31;
    const int wm = (wid >> 2) * 64;
    const int wn = (wid & 3) * 32;
    const int g = lane >> 2, tg = lane & 3;
    const int lr = tid >> 3;
    const int lc = (tid & 7) * 4;

    const float* Ap = A + (size_t)m0 * Dd;
    const float* Wp = W + (size_t)n0 * Dd;

    float acc[4][4][4];
#pragma unroll
    for (int i = 0; i < 4; i++)
#pragma unroll
        for (int j = 0; j < 4; j++)
#pragma unroll
            for (int r = 0; r < 4; r++) acc[i][j][r] = 0.f;

    float4 ra[4], rb[4];
#pragma unroll
    for (int i = 0; i < 4; i++) {
        ra[i] = *(const float4*)(Ap + (size_t)(lr + 32 * i) * Dd + lc);
        rb[i] = *(const float4*)(Wp + (size_t)(lr + 32 * i) * Dd + lc);
    }

    for (int k0 = 0; k0 < Dd; k0 += 32) {
        __syncthreads();
#pragma unroll
        for (int i = 0; i < 4; i++) {
            uint32_t* ap = &As[lr + 32 * i][lc];
            ap[0] = f2tf32(ra[i].x); ap[1] = f2tf32(ra[i].y);
            ap[2] = f2tf32(ra[i].z); ap[3] = f2tf32(ra[i].w);
            uint32_t* bp = &Bs[lr + 32 * i][lc];
            bp[0] = f2tf32(rb[i].x); bp[1] = f2tf32(rb[i].y);
            bp[2] = f2tf32(rb[i].z); bp[3] = f2tf32(rb[i].w);
        }
        __syncthreads();

        if (k0 + 32 < Dd) {
#pragma unroll
            for (int i = 0; i < 4; i++) {
                ra[i] = *(const float4*)(Ap + (size_t)(lr + 32 * i) * Dd + k0 + 32 + lc);
                rb[i] = *(const float4*)(Wp + (size_t)(lr + 32 * i) * Dd + k0 + 32 + lc);
            }
        }

#pragma unroll
        for (int ks = 0; ks < 4; ++ks) {
            const int kb = ks * 8;
            uint32_t af[4][4], bf[4][2];
#pragma unroll
            for (int mi = 0; mi < 4; mi++) {
                const int row = wm + mi * 16;
                af[mi][0] = As[row + g][kb + tg];
                af[mi][1] = As[row + g + 8][kb + tg];
                af[mi][2] = As[row + g][kb + tg + 4];
                af[mi][3] = As[row + g + 8][kb + tg + 4];
            }
#pragma unroll
            for (int ni = 0; ni < 4; ni++) {
                const int col = wn + ni * 8;
                bf[ni][0] = Bs[col + g][kb + tg];
                bf[ni][1] = Bs[col + g][kb + tg + 4];
            }
#pragma unroll
            for (int mi = 0; mi < 4; mi++)
#pragma unroll
                for (int ni = 0; ni < 4; ni++)
                    mma8(acc[mi][ni], af[mi][0], af[mi][1], af[mi][2], af[mi][3],
                         bf[ni][0], bf[ni][1]);
        }
    }

#pragma unroll
    for (int mi = 0; mi < 4; mi++)
#pragma unroll
        for (int ni = 0; ni < 4; ni++) {
            const int r0 = m0 + wm + mi * 16 + g;
            const int cc = n0 + wn + ni * 8 + 2 * tg;
            *(float2*)&C[(size_t)r0 * Dd + cc] =
                make_float2(acc[mi][ni][0], acc[mi][ni][1]);
            *(float2*)&C[(size_t)(r0 + 8) * Dd + cc] =
                make_float2(acc[mi][ni][2], acc[mi][ni][3]);
        }
}

// ---------------------------------------------------------------------------
// Interleaved RoPE on Q and K in place.
// ---------------------------------------------------------------------------
__global__ void rope_kernel(const float* __restrict__ cosT,
                            const float* __restrict__ sinT) {
    size_t i = (size_t)blockIdx.x * blockDim.x + threadIdx.x;
    int colp = (int)(i & (Dd / 2 - 1));
    size_t row = i >> 10;
    int s = (int)(row & (Ss - 1));
    int h = colp >> 6, p = colp & 63;
    float c  = cosT[s * Dhh + 2 * p];
    float sn = sinT[s * Dhh + 2 * p];
    size_t base = row * Dd + h * Dhh + 2 * p;
    float2 q = *(float2*)&g_Q[base];
    float2 k = *(float2*)&g_K[base];
    float2 qo, ko;
    qo.x = q.x * c - q.y * sn;  qo.y = q.y * c + q.x * sn;
    ko.x = k.x * c - k.y * sn;  ko.y = k.y * c + k.x * sn;
    *(float2*)&g_Q[base] = qo;
    *(float2*)&g_K[base] = ko;
}

// ---------------------------------------------------------------------------
// tf32-mma causal flash attention + final softmax over Dh.
// Br=128, Bc=64. 8 warps, warp w owns rows [w*16, w*16+16) full width.
// K/V double-buffered via cp.async. P stays in registers (shuffle remap).
// Grid: (16, B*H), heavy tiles first. Block: 256 threads.
// ---------------------------------------------------------------------------
#define QP 132

__global__ void __launch_bounds__(256) attn_mma(float* __restrict__ out) {
    extern __shared__ uint32_t sm[];
    uint32_t* Qs = sm;                         // 128 x 132
    uint32_t* Kb[2] = { sm + 128 * QP, sm + 128 * QP + 64 * QP };
    uint32_t* Vb[2] = { sm + 128 * QP + 2 * 64 * QP, sm + 128 * QP + 3 * 64 * QP };

    const int qt = 15 - blockIdx.x;            // heavy first
    const int bh = blockIdx.y;
    const int b = bh >> 4, h = bh & 15;
    const int tid = threadIdx.x, wid = tid >> 5, lane = tid & 31;
    const int g = lane >> 2, tg = lane & 3;
    const int r0w = wid * 16;
    const size_t base = ((size_t)b * Ss) * Dd + h * Dhh;
    const float qscale = 0.08838834764831845f * 1.4426950408889634f; // rsqrt(Dh)*log2e

    // Q tile: scaled + tf32, once.
    for (int e = tid * 4; e < 128 * 128; e += 1024) {
        int r = e >> 7, c = e & 127;
        float4 v = *(const float4*)&g_Q[base + (size_t)(qt * 128 + r) * Dd + c];
        uint4 u;
        u.x = f2tf32(v.x * qscale); u.y = f2tf32(v.y * qscale);
        u.z = f2tf32(v.z * qscale); u.w = f2tf32(v.w * qscale);
        *(uint4*)&Qs[r * QP + c] = u;
    }

    const int jmax = 2 * qt + 1;
    const uint32_t aK0 = smem_u32(Kb[0]), aK1 = smem_u32(Kb[1]);
    const uint32_t aV0 = smem_u32(Vb[0]), aV1 = smem_u32(Vb[1]);

    float oa[16][4];
#pragma unroll
    for (int ni = 0; ni < 16; ni++)
#pragma unroll
        for (int r = 0; r < 4; r++) oa[ni][r] = 0.f;
    float m0 = -1e30f, m1 = -1e30f, l0 = 0.f, l1 = 0.f;

    // prefetch tile 0
    {
        const float* Ksrc = &g_K[base];
        const float* Vsrc = &g_V[base];
        for (int e = tid * 4; e < 64 * 128; e += 1024) {
            int r = e >> 7, c = e & 127;
            cpa16(aK0 + (uint32_t)(r * QP + c) * 4, Ksrc + (size_t)r * Dd + c);
            cpa16(aV0 + (uint32_t)(r * QP + c) * 4, Vsrc + (size_t)r * Dd + c);
        }
        asm volatile("cp.async.commit_group;" ::: "memory");
    }

    for (int j = 0; j <= jmax; ++j) {
        __syncthreads();   // prior-iter reads of the buffer we're about to fill are done
        if (j < jmax) {
            const int jn = j + 1;
            const uint32_t kd = (jn & 1) ? aK1 : aK0;
            const uint32_t vd = (jn & 1) ? aV1 : aV0;
            const float* Ksrc = &g_K[base + (size_t)(jn * 64) * Dd];
            const float* Vsrc = &g_V[base + (size_t)(jn * 64) * Dd];
            for (int e = tid * 4; e < 64 * 128; e += 1024) {
                int r = e >> 7, c = e & 127;
                cpa16(kd + (uint32_t)(r * QP + c) * 4, Ksrc + (size_t)r * Dd + c);
                cpa16(vd + (uint32_t)(r * QP + c) * 4, Vsrc + (size_t)r * Dd + c);
            }
            asm volatile("cp.async.commit_group;" ::: "memory");
            asm volatile("cp.async.wait_group 1;" ::: "memory");
        } else {
            asm volatile("cp.async.wait_group 0;" ::: "memory");
        }
        __syncthreads();

        const uint32_t* Ks = Kb[j & 1];
        const uint32_t* Vs = Vb[j & 1];

        // ---- S = Q @ K^T -------------------------------------------------
        float sc[8][4];
#pragma unroll
        for (int ni = 0; ni < 8; ni++)
#pragma unroll
            for (int r = 0; r < 4; r++) sc[ni][r] = 0.f;

#pragma unroll
        for (int ks = 0; ks < 16; ++ks) {
            const int kb = ks * 8;
            uint32_t a0 = Qs[(r0w + g) * QP + kb + tg];
            uint32_t a1 = Qs[(r0w + g + 8) * QP + kb + tg];
            uint32_t a2 = Qs[(r0w + g) * QP + kb + tg + 4];
            uint32_t a3 = Qs[(r0w + g + 8) * QP + kb + tg + 4];
#pragma unroll
            for (int ni = 0; ni < 8; ++ni) {
                uint32_t b0 = Ks[(8 * ni + g) * QP + kb + tg];
                uint32_t b1 = Ks[(8 * ni + g) * QP + kb + tg + 4];
                mma8(sc[ni], a0, a1, a2, a3, b0, b1);
            }
        }

        // ---- causal mask (only the two diagonal tiles) -------------------
        if (j >= 2 * qt) {
            const int rg = qt * 128 + r0w + g;
#pragma unroll
            for (int ni = 0; ni < 8; ++ni) {
                const int cb = j * 64 + 8 * ni + 2 * tg;
                if (cb     > rg)     sc[ni][0] = -1e30f;
                if (cb + 1 > rg)     sc[ni][1] = -1e30f;
                if (cb     > rg + 8) sc[ni][2] = -1e30f;
                if (cb + 1 > rg + 8) sc[ni][3] = -1e30f;
            }
        }

        // ---- online softmax (base-2 domain, quad reductions) -------------
        float tm0 = -1e30f, tm1 = -1e30f;
#pragma unroll
        for (int ni = 0; ni < 8; ++ni) {
            tm0 = fmaxf(tm0, fmaxf(sc[ni][0], sc[ni][1]));
            tm1 = fmaxf(tm1, fmaxf(sc[ni][2], sc[ni][3]));
        }
        tm0 = fmaxf(tm0, __shfl_xor_sync(0xffffffffu, tm0, 1));
        tm0 = fmaxf(tm0, __shfl_xor_sync(0xffffffffu, tm0, 2));
        tm1 = fmaxf(tm1, __shfl_xor_sync(0xffffffffu, tm1, 1));
        tm1 = fmaxf(tm1, __shfl_xor_sync(0xffffffffu, tm1, 2));
        const float nm0 = fmaxf(m0, tm0), nm1 = fmaxf(m1, tm1);
        const float e0 = ex2(m0 - nm0), e1 = ex2(m1 - nm1);
        m0 = nm0; m1 = nm1;
        float ps0 = 0.f, ps1 = 0.f;
#pragma unroll
        for (int ni = 0; ni < 8; ++ni) {
            sc[ni][0] = ex2(sc[ni][0] - nm0); ps0 += sc[ni][0];
            sc[ni][1] = ex2(sc[ni][1] - nm0); ps0 += sc[ni][1];
            sc[ni][2] = ex2(sc[ni][2] - nm1); ps1 += sc[ni][2];
            sc[ni][3] = ex2(sc[ni][3] - nm1); ps1 += sc[ni][3];
        }
        ps0 += __shfl_xor_sync(0xffffffffu, ps0, 1);
        ps0 += __shfl_xor_sync(0xffffffffu, ps0, 2);
        ps1 += __shfl_xor_sync(0xffffffffu, ps1, 1);
        ps1 += __shfl_xor_sync(0xffffffffu, ps1, 2);
        l0 = l0 * e0 + ps0;
        l1 = l1 * e1 + ps1;
#pragma unroll
        for (int ni = 0; ni < 16; ++ni) {
            oa[ni][0] *= e0; oa[ni][1] *= e0;
            oa[ni][2] *= e1; oa[ni][3] *= e1;
        }

        // ---- O += P @ V  (P stays in registers via quad shuffles) --------
        const int srcA = (lane & 0x1c) | (tg >> 1);
        const int srcB = srcA + 2;
        const bool odd = tg & 1;
#pragma unroll
        for (int ks = 0; ks < 8; ++ks) {
            float s0 = __shfl_sync(0xffffffffu, sc[ks][0], srcA);
            float s1 = __shfl_sync(0xffffffffu, sc[ks][1], srcA);
            float s2 = __shfl_sync(0xffffffffu, sc[ks][2], srcA);
            float s3 = __shfl_sync(0xffffffffu, sc[ks][3], srcA);
            float u0 = __shfl_sync(0xffffffffu, sc[ks][0], srcB);
            float u1 = __shfl_sync(0xffffffffu, sc[ks][1], srcB);
            float u2 = __shfl_sync(0xffffffffu, sc[ks][2], srcB);
            float u3 = __shfl_sync(0xffffffffu, sc[ks][3], srcB);
            uint32_t a0 = f2tf32(odd ? s1 : s0);
            uint32_t a1 = f2tf32(odd ? s3 : s2);
            uint32_t a2 = f2tf32(odd ? u1 : u0);
            uint32_t a3 = f2tf32(odd ? u3 : u2);
            const int kb = ks * 8;
#pragma unroll
            for (int ni = 0; ni < 16; ++ni) {
                uint32_t b0 = Vs[(kb + tg) * QP + 8 * ni + g];
                uint32_t b1 = Vs[(kb + tg + 4) * QP + 8 * ni + g];
                mma8(oa[ni], a0, a1, a2, a3, b0, b1);
            }
        }
    }

    // ---- epilogue: /l, softmax over Dh, store ----------------------------
    const float LOG2E = 1.4426950408889634f;
    const float inv0 = 1.f / l0, inv1 = 1.f / l1;
#pragma unroll
    for (int ni = 0; ni < 16; ++ni) {
        oa[ni][0] *= inv0; oa[ni][1] *= inv0;
        oa[ni][2] *= inv1; oa[ni][3] *= inv1;
    }
    float mx0 = -1e30f, mx1 = -1e30f;
#pragma unroll
    for (int ni = 0; ni < 16; ++ni) {
        mx0 = fmaxf(mx0, fmaxf(oa[ni][0], oa[ni][1]));
        mx1 = fmaxf(mx1, fmaxf(oa[ni][2], oa[ni][3]));
    }
    mx0 = fmaxf(mx0, __shfl_xor_sync(0xffffffffu, mx0, 1));
    mx0 = fmaxf(mx0, __shfl_xor_sync(0xffffffffu, mx0, 2));
    mx1 = fmaxf(mx1, __shfl_xor_sync(0xffffffffu, mx1, 1));
    mx1 = fmaxf(mx1, __shfl_xor_sync(0xffffffffu, mx1, 2));
    float s0 = 0.f, s1 = 0.f;
#pragma unroll
    for (int ni = 0; ni < 16; ++ni) {
        oa[ni][0] = ex2((oa[ni][0] - mx0) * LOG2E); s0 += oa[ni][0];
        oa[ni][1] = ex2((oa[ni][1] - mx0) * LOG2E); s0 += oa[ni][1];
        oa[ni][2] = ex2((oa[ni][2] - mx1) * LOG2E); s1 += oa[ni][2];
        oa[ni][3] = ex2((oa[ni][3] - mx1) * LOG2E); s1 += oa[ni][3];
    }
    s0 += __shfl_xor_sync(0xffffffffu, s0, 1);
    s0 += __shfl_xor_sync(0xffffffffu, s0, 2);
    s1 += __shfl_xor_sync(0xffffffffu, s1, 1);
    s1 += __shfl_xor_sync(0xffffffffu, s1, 2);
    const float r0s = 1.f / s0, r1s = 1.f / s1;
    const int row0 = qt * 128 + r0w + g;
#pragma unroll
    for (int ni = 0; ni < 16; ++ni) {
        const int col = 8 * ni + 2 * tg;
        *(float2*)&out[base + (size_t)row0 * Dd + col] =
            make_float2(oa[ni][0] * r0s, oa[ni][1] * r0s);
        *(float2*)&out[base + (size_t)(row0 + 8) * Dd + col] =
            make_float2(oa[ni][2] * r1s, oa[ni][3] * r1s);
    }
}

static const size_t ATTN_SMEM = (128 * QP + 4 * 64 * QP) * sizeof(uint32_t); // 202752 B

extern "C" void kernel_launch(void* const* d_in, const int* in_sizes, int n_in,
                              void* d_out, int out_size) {
    const float* x  = (const float*)d_in[0];
    const float* wq = (const float*)d_in[1];
    const float* wk = (const float*)d_in[2];
    const float* wv = (const float*)d_in[3];
    const float* rc = (const float*)d_in[4];
    const float* rs = (const float*)d_in[5];
    float* out = (float*)d_out;

    float *Qp, *Kp, *Vp;
    cudaGetSymbolAddress((void**)&Qp, g_Q);
    cudaGetSymbolAddress((void**)&Kp, g_K);
    cudaGetSymbolAddress((void**)&Vp, g_V);

    cudaFuncSetAttribute(attn_mma, cudaFuncAttributeMaxDynamicSharedMemorySize,
                         (int)ATTN_SMEM);

    dim3 gg(Dd / 128, Mrows / 128);
    tgemm_nt<<<gg, 256>>>(x, wq, Qp);
    tgemm_nt<<<gg, 256>>>(x, wk, Kp);
    tgemm_nt<<<gg, 256>>>(x, wv, Vp);

    rope_kernel<<<(Mrows * (Dd / 2)) / 256, 256>>>(rc, rs);

    attn_mma<<<dim3(Ss / 128, Bb * Hh), 256, ATTN_SMEM>>>(out);
}

// round 4
// speedup vs baseline: 4.0449x; 1.0661x over previous
#include <cuda_runtime.h>
#include <math.h>
#include <stdint.h>

#define Bb   2
#define Ss   2048
#define Dd   2048
#define Hh   16
#define Dhh  128
#define Mrows (Bb * Ss)   // 4096

__device__ float g_Q[(size_t)Mrows * Dd];
__device__ float g_K[(size_t)Mrows * Dd];
__device__ float g_V[(size_t)Mrows * Dd];

__device__ __forceinline__ uint32_t f2tf32(float x) {
    uint32_t u;
    asm("cvt.rna.tf32.f32 %0, %1;" : "=r"(u) : "f"(x));
    return u;
}
__device__ __forceinline__ float ex2(float x) {
    float y;
    asm("ex2.approx.ftz.f32 %0, %1;" : "=f"(y) : "f"(x));
    return y;
}
__device__ __forceinline__ uint32_t smem_u32(const void* p) {
    uint32_t a;
    asm("{ .reg .u64 t; cvta.to.shared.u64 t, %1; cvt.u32.u64 %0, t; }"
        : "=r"(a) : "l"(p));
    return a;
}
__device__ __forceinline__ void cpa16(uint32_t dst, const void* src) {
    asm volatile("cp.async.cg.shared.global [%0], [%1], 16;" :: "r"(dst), "l"(src));
}
__device__ __forceinline__ void mma8(float* c, uint32_t a0, uint32_t a1,
                                     uint32_t a2, uint32_t a3,
                                     uint32_t b0, uint32_t b1) {
    asm volatile(
        "mma.sync.aligned.m16n8k8.row.col.f32.tf32.tf32.f32 "
        "{%0,%1,%2,%3}, {%4,%5,%6,%7}, {%8,%9}, {%0,%1,%2,%3};"
        : "+f"(c[0]), "+f"(c[1]), "+f"(c[2]), "+f"(c[3])
        : "r"(a0), "r"(a1), "r"(a2), "r"(a3), "r"(b0), "r"(b1));
}

// ---------------------------------------------------------------------------
// Fused Q/K/V projection: C_z = A @ W_z^T, rope applied in epilogue for z<2.
// 128x128 tile, BK=32, cp.async 2-stage double buffer, raw f32 -> tf32 (RZ).
// Grid (16, 32, 3), block 256 (8 warps, warp tile 64x32).
// ---------------------------------------------------------------------------
#define GSTAGE (128 * 36)

__global__ void __launch_bounds__(256, 2)
tgemm_fused(const float* __restrict__ A,
            const float* __restrict__ wq, const float* __restrict__ wk,
            const float* __restrict__ wv,
            const float* __restrict__ cosT, const float* __restrict__ sinT) {
    extern __shared__ uint32_t smb[];
    uint32_t* As = smb;                    // 2 x 128 x 36
    uint32_t* Bs = smb + 2 * GSTAGE;       // 2 x 128 x 36

    const int z = blockIdx.z;
    const float* W = (z == 0) ? wq : (z == 1) ? wk : wv;
    float* C = (z == 0) ? g_Q : (z == 1) ? g_K : g_V;

    const int tid = threadIdx.x;
    const int m0 = blockIdx.y * 128, n0 = blockIdx.x * 128;
    const int wid = tid >> 5, lane = tid & 31;
    const int wm = (wid >> 2) * 64;
    const int wn = (wid & 3) * 32;
    const int g = lane >> 2, tg = lane & 3;
    const int lr = tid >> 3;            // 0..31
    const int lc = (tid & 7) * 4;       // 0..28

    const float* Ap = A + (size_t)m0 * Dd;
    const float* Wp = W + (size_t)n0 * Dd;
    const uint32_t aA = smem_u32(As), aB = smem_u32(Bs);

    float acc[4][4][4];
#pragma unroll
    for (int i = 0; i < 4; i++)
#pragma unroll
        for (int j = 0; j < 4; j++)
#pragma unroll
            for (int r = 0; r < 4; r++) acc[i][j][r] = 0.f;

    // prologue: stage 0
#pragma unroll
    for (int i = 0; i < 4; i++) {
        uint32_t off = (uint32_t)((lr + 32 * i) * 36 + lc) * 4;
        cpa16(aA + off, Ap + (size_t)(lr + 32 * i) * Dd + lc);
        cpa16(aB + off, Wp + (size_t)(lr + 32 * i) * Dd + lc);
    }
    asm volatile("cp.async.commit_group;" ::: "memory");

    const int NT = Dd / 32;  // 64
    for (int t = 0; t < NT; ++t) {
        const int cur = t & 1;
        __syncthreads();     // compute(t-1) finished reading buf (t+1)&1
        if (t + 1 < NT) {
            const int nxt = (t + 1) & 1;
            const int k0 = (t + 1) * 32;
#pragma unroll
            for (int i = 0; i < 4; i++) {
                uint32_t off = (uint32_t)(nxt * GSTAGE + (lr + 32 * i) * 36 + lc) * 4;
                cpa16(aA + off, Ap + (size_t)(lr + 32 * i) * Dd + k0 + lc);
                cpa16(aB + off, Wp + (size_t)(lr + 32 * i) * Dd + k0 + lc);
            }
            asm volatile("cp.async.commit_group;" ::: "memory");
            asm volatile("cp.async.wait_group 1;" ::: "memory");
        } else {
            asm volatile("cp.async.wait_group 0;" ::: "memory");
        }
        __syncthreads();

        const uint32_t* Ab = As + cur * GSTAGE;
        const uint32_t* Bbf = Bs + cur * GSTAGE;
#pragma unroll
        for (int ks = 0; ks < 4; ++ks) {
            const int kb = ks * 8;
            uint32_t af[4][4], bf[4][2];
#pragma unroll
            for (int mi = 0; mi < 4; mi++) {
                const int row = wm + mi * 16;
                af[mi][0] = Ab[(row + g) * 36 + kb + tg];
                af[mi][1] = Ab[(row + g + 8) * 36 + kb + tg];
                af[mi][2] = Ab[(row + g) * 36 + kb + tg + 4];
                af[mi][3] = Ab[(row + g + 8) * 36 + kb + tg + 4];
            }
#pragma unroll
            for (int ni = 0; ni < 4; ni++) {
                const int col = wn + ni * 8;
                bf[ni][0] = Bbf[(col + g) * 36 + kb + tg];
                bf[ni][1] = Bbf[(col + g) * 36 + kb + tg + 4];
            }
#pragma unroll
            for (int mi = 0; mi < 4; mi++)
#pragma unroll
                for (int ni = 0; ni < 4; ni++)
                    mma8(acc[mi][ni], af[mi][0], af[mi][1], af[mi][2], af[mi][3],
                         bf[ni][0], bf[ni][1]);
        }
    }

    // epilogue: rope (z<2) + store
#pragma unroll
    for (int mi = 0; mi < 4; mi++)
#pragma unroll
        for (int ni = 0; ni < 4; ni++) {
            const int r0 = m0 + wm + mi * 16 + g;
            const int cc = n0 + wn + ni * 8 + 2 * tg;
            float c0 = acc[mi][ni][0], c1 = acc[mi][ni][1];
            float c2 = acc[mi][ni][2], c3 = acc[mi][ni][3];
            if (z < 2) {
                const int d = cc & (Dhh - 1);
                const int s0 = r0 & (Ss - 1), s1 = (r0 + 8) & (Ss - 1);
                float cs0 = cosT[s0 * Dhh + d], sn0 = sinT[s0 * Dhh + d];
                float cs1 = cosT[s1 * Dhh + d], sn1 = sinT[s1 * Dhh + d];
                float x0 = c0 * cs0 - c1 * sn0, y0 = c1 * cs0 + c0 * sn0;
                float x1 = c2 * cs1 - c3 * sn1, y1 = c3 * cs1 + c2 * sn1;
                c0 = x0; c1 = y0; c2 = x1; c3 = y1;
            }
            *(float2*)&C[(size_t)r0 * Dd + cc]       = make_float2(c0, c1);
            *(float2*)&C[(size_t)(r0 + 8) * Dd + cc] = make_float2(c2, c3);
        }
}

// ---------------------------------------------------------------------------
// tf32-mma causal flash attention + final softmax over Dh (unchanged, R2).
// ---------------------------------------------------------------------------
#define QP 132

__global__ void __launch_bounds__(256) attn_mma(float* __restrict__ out) {
    extern __shared__ uint32_t sm[];
    uint32_t* Qs = sm;                         // 128 x 132
    uint32_t* Kb[2] = { sm + 128 * QP, sm + 128 * QP + 64 * QP };
    uint32_t* Vb[2] = { sm + 128 * QP + 2 * 64 * QP, sm + 128 * QP + 3 * 64 * QP };

    const int qt = 15 - blockIdx.x;            // heavy first
    const int bh = blockIdx.y;
    const int b = bh >> 4, h = bh & 15;
    const int tid = threadIdx.x, wid = tid >> 5, lane = tid & 31;
    const int g = lane >> 2, tg = lane & 3;
    const int r0w = wid * 16;
    const size_t base = ((size_t)b * Ss) * Dd + h * Dhh;
    const float qscale = 0.08838834764831845f * 1.4426950408889634f;

    for (int e = tid * 4; e < 128 * 128; e += 1024) {
        int r = e >> 7, c = e & 127;
        float4 v = *(const float4*)&g_Q[base + (size_t)(qt * 128 + r) * Dd + c];
        uint4 u;
        u.x = f2tf32(v.x * qscale); u.y = f2tf32(v.y * qscale);
        u.z = f2tf32(v.z * qscale); u.w = f2tf32(v.w * qscale);
        *(uint4*)&Qs[r * QP + c] = u;
    }

    const int jmax = 2 * qt + 1;
    const uint32_t aK0 = smem_u32(Kb[0]), aK1 = smem_u32(Kb[1]);
    const uint32_t aV0 = smem_u32(Vb[0]), aV1 = smem_u32(Vb[1]);

    float oa[16][4];
#pragma unroll
    for (int ni = 0; ni < 16; ni++)
#pragma unroll
        for (int r = 0; r < 4; r++) oa[ni][r] = 0.f;
    float m0 = -1e30f, m1 = -1e30f, l0 = 0.f, l1 = 0.f;

    {
        const float* Ksrc = &g_K[base];
        const float* Vsrc = &g_V[base];
        for (int e = tid * 4; e < 64 * 128; e += 1024) {
            int r = e >> 7, c = e & 127;
            cpa16(aK0 + (uint32_t)(r * QP + c) * 4, Ksrc + (size_t)r * Dd + c);
            cpa16(aV0 + (uint32_t)(r * QP + c) * 4, Vsrc + (size_t)r * Dd + c);
        }
        asm volatile("cp.async.commit_group;" ::: "memory");
    }

    for (int j = 0; j <= jmax; ++j) {
        __syncthreads();
        if (j < jmax) {
            const int jn = j + 1;
            const uint32_t kd = (jn & 1) ? aK1 : aK0;
            const uint32_t vd = (jn & 1) ? aV1 : aV0;
            const float* Ksrc = &g_K[base + (size_t)(jn * 64) * Dd];
            const float* Vsrc = &g_V[base + (size_t)(jn * 64) * Dd];
            for (int e = tid * 4; e < 64 * 128; e += 1024) {
                int r = e >> 7, c = e & 127;
                cpa16(kd + (uint32_t)(r * QP + c) * 4, Ksrc + (size_t)r * Dd + c);
                cpa16(vd + (uint32_t)(r * QP + c) * 4, Vsrc + (size_t)r * Dd + c);
            }
            asm volatile("cp.async.commit_group;" ::: "memory");
            asm volatile("cp.async.wait_group 1;" ::: "memory");
        } else {
            asm volatile("cp.async.wait_group 0;" ::: "memory");
        }
        __syncthreads();

        const uint32_t* Ks = Kb[j & 1];
        const uint32_t* Vs = Vb[j & 1];

        float sc[8][4];
#pragma unroll
        for (int ni = 0; ni < 8; ni++)
#pragma unroll
            for (int r = 0; r < 4; r++) sc[ni][r] = 0.f;

#pragma unroll
        for (int ks = 0; ks < 16; ++ks) {
            const int kb = ks * 8;
            uint32_t a0 = Qs[(r0w + g) * QP + kb + tg];
            uint32_t a1 = Qs[(r0w + g + 8) * QP + kb + tg];
            uint32_t a2 = Qs[(r0w + g) * QP + kb + tg + 4];
            uint32_t a3 = Qs[(r0w + g + 8) * QP + kb + tg + 4];
#pragma unroll
            for (int ni = 0; ni < 8; ++ni) {
                uint32_t b0 = Ks[(8 * ni + g) * QP + kb + tg];
                uint32_t b1 = Ks[(8 * ni + g) * QP + kb + tg + 4];
                mma8(sc[ni], a0, a1, a2, a3, b0, b1);
            }
        }

        if (j >= 2 * qt) {
            const int rg = qt * 128 + r0w + g;
#pragma unroll
            for (int ni = 0; ni < 8; ++ni) {
                const int cb = j * 64 + 8 * ni + 2 * tg;
                if (cb     > rg)     sc[ni][0] = -1e30f;
                if (cb + 1 > rg)     sc[ni][1] = -1e30f;
                if (cb     > rg + 8) sc[ni][2] = -1e30f;
                if (cb + 1 > rg + 8) sc[ni][3] = -1e30f;
            }
        }

        float tm0 = -1e30f, tm1 = -1e30f;
#pragma unroll
        for (int ni = 0; ni < 8; ++ni) {
            tm0 = fmaxf(tm0, fmaxf(sc[ni][0], sc[ni][1]));
            tm1 = fmaxf(tm1, fmaxf(sc[ni][2], sc[ni][3]));
        }
        tm0 = fmaxf(tm0, __shfl_xor_sync(0xffffffffu, tm0, 1));
        tm0 = fmaxf(tm0, __shfl_xor_sync(0xffffffffu, tm0, 2));
        tm1 = fmaxf(tm1, __shfl_xor_sync(0xffffffffu, tm1, 1));
        tm1 = fmaxf(tm1, __shfl_xor_sync(0xffffffffu, tm1, 2));
        const float nm0 = fmaxf(m0, tm0), nm1 = fmaxf(m1, tm1);
        const float e0 = ex2(m0 - nm0), e1 = ex2(m1 - nm1);
        m0 = nm0; m1 = nm1;
        float ps0 = 0.f, ps1 = 0.f;
#pragma unroll
        for (int ni = 0; ni < 8; ++ni) {
            sc[ni][0] = ex2(sc[ni][0] - nm0); ps0 += sc[ni][0];
            sc[ni][1] = ex2(sc[ni][1] - nm0); ps0 += sc[ni][1];
            sc[ni][2] = ex2(sc[ni][2] - nm1); ps1 += sc[ni][2];
            sc[ni][3] = ex2(sc[ni][3] - nm1); ps1 += sc[ni][3];
        }
        ps0 += __shfl_xor_sync(0xffffffffu, ps0, 1);
        ps0 += __shfl_xor_sync(0xffffffffu, ps0, 2);
        ps1 += __shfl_xor_sync(0xffffffffu, ps1, 1);
        ps1 += __shfl_xor_sync(0xffffffffu, ps1, 2);
        l0 = l0 * e0 + ps0;
        l1 = l1 * e1 + ps1;
#pragma unroll
        for (int ni = 0; ni < 16; ++ni) {
            oa[ni][0] *= e0; oa[ni][1] *= e0;
            oa[ni][2] *= e1; oa[ni][3] *= e1;
        }

        const int srcA = (lane & 0x1c) | (tg >> 1);
        const int srcB = srcA + 2;
        const bool odd = tg & 1;
#pragma unroll
        for (int ks = 0; ks < 8; ++ks) {
            float s0 = __shfl_sync(0xffffffffu, sc[ks][0], srcA);
            float s1 = __shfl_sync(0xffffffffu, sc[ks][1], srcA);
            float s2 = __shfl_sync(0xffffffffu, sc[ks][2], srcA);
            float s3 = __shfl_sync(0xffffffffu, sc[ks][3], srcA);
            float u0 = __shfl_sync(0xffffffffu, sc[ks][0], srcB);
            float u1 = __shfl_sync(0xffffffffu, sc[ks][1], srcB);
            float u2 = __shfl_sync(0xffffffffu, sc[ks][2], srcB);
            float u3 = __shfl_sync(0xffffffffu, sc[ks][3], srcB);
            uint32_t a0 = f2tf32(odd ? s1 : s0);
            uint32_t a1 = f2tf32(odd ? s3 : s2);
            uint32_t a2 = f2tf32(odd ? u1 : u0);
            uint32_t a3 = f2tf32(odd ? u3 : u2);
            const int kb = ks * 8;
#pragma unroll
            for (int ni = 0; ni < 16; ++ni) {
                uint32_t b0 = Vs[(kb + tg) * QP + 8 * ni + g];
                uint32_t b1 = Vs[(kb + tg + 4) * QP + 8 * ni + g];
                mma8(oa[ni], a0, a1, a2, a3, b0, b1);
            }
        }
    }

    const float LOG2E = 1.4426950408889634f;
    const float inv0 = 1.f / l0, inv1 = 1.f / l1;
#pragma unroll
    for (int ni = 0; ni < 16; ++ni) {
        oa[ni][0] *= inv0; oa[ni][1] *= inv0;
        oa[ni][2] *= inv1; oa[ni][3] *= inv1;
    }
    float mx0 = -1e30f, mx1 = -1e30f;
#pragma unroll
    for (int ni = 0; ni < 16; ++ni) {
        mx0 = fmaxf(mx0, fmaxf(oa[ni][0], oa[ni][1]));
        mx1 = fmaxf(mx1, fmaxf(oa[ni][2], oa[ni][3]));
    }
    mx0 = fmaxf(mx0, __shfl_xor_sync(0xffffffffu, mx0, 1));
    mx0 = fmaxf(mx0, __shfl_xor_sync(0xffffffffu, mx0, 2));
    mx1 = fmaxf(mx1, __shfl_xor_sync(0xffffffffu, mx1, 1));
    mx1 = fmaxf(mx1, __shfl_xor_sync(0xffffffffu, mx1, 2));
    float s0 = 0.f, s1 = 0.f;
#pragma unroll
    for (int ni = 0; ni < 16; ++ni) {
        oa[ni][0] = ex2((oa[ni][0] - mx0) * LOG2E); s0 += oa[ni][0];
        oa[ni][1] = ex2((oa[ni][1] - mx0) * LOG2E); s0 += oa[ni][1];
        oa[ni][2] = ex2((oa[ni][2] - mx1) * LOG2E); s1 += oa[ni][2];
        oa[ni][3] = ex2((oa[ni][3] - mx1) * LOG2E); s1 += oa[ni][3];
    }
    s0 += __shfl_xor_sync(0xffffffffu, s0, 1);
    s0 += __shfl_xor_sync(0xffffffffu, s0, 2);
    s1 += __shfl_xor_sync(0xffffffffu, s1, 1);
    s1 += __shfl_xor_sync(0xffffffffu, s1, 2);
    const float r0s = 1.f / s0, r1s = 1.f / s1;
    const int row0 = qt * 128 + r0w + g;
#pragma unroll
    for (int ni = 0; ni < 16; ++ni) {
        const int col = 8 * ni + 2 * tg;
        *(float2*)&out[base + (size_t)row0 * Dd + col] =
            make_float2(oa[ni][0] * r0s, oa[ni][1] * r0s);
        *(float2*)&out[base + (size_t)(row0 + 8) * Dd + col] =
            make_float2(oa[ni][2] * r1s, oa[ni][3] * r1s);
    }
}

static const size_t ATTN_SMEM = (128 * QP + 4 * 64 * QP) * sizeof(uint32_t); // 202752 B
static const size_t GEMM_SMEM = 4 * GSTAGE * sizeof(uint32_t);               // 73728 B

extern "C" void kernel_launch(void* const* d_in, const int* in_sizes, int n_in,
                              void* d_out, int out_size) {
    const float* x  = (const float*)d_in[0];
    const float* wq = (const float*)d_in[1];
    const float* wk = (const float*)d_in[2];
    const float* wv = (const float*)d_in[3];
    const float* rc = (const float*)d_in[4];
    const float* rs = (const float*)d_in[5];
    float* out = (float*)d_out;

    cudaFuncSetAttribute(tgemm_fused, cudaFuncAttributeMaxDynamicSharedMemorySize,
                         (int)GEMM_SMEM);
    cudaFuncSetAttribute(attn_mma, cudaFuncAttributeMaxDynamicSharedMemorySize,
                         (int)ATTN_SMEM);

    dim3 gg(Dd / 128, Mrows / 128, 3);   // (16, 32, 3)
    tgemm_fused<<<gg, 256, GEMM_SMEM>>>(x, wq, wk, wv, rc, rs);

    attn_mma<<<dim3(Ss / 128, Bb * Hh), 256, ATTN_SMEM>>>(out);
}